// round 11
// baseline (speedup 1.0000x reference)
#include <cuda_runtime.h>
#include <cuda_bf16.h>
#include <math_constants.h>

#define Bc 2
#define Cc 256
#define Hc 256
#define Wc 256
#define MIDc 16
#define HWc 65536

typedef unsigned long long u64;

__device__ float g_xlow[(size_t)Bc * HWc * MIDc];    // [b][p][m] interleaved
__device__ float g_outlow[(size_t)Bc * HWc * MIDc];  // [b][p][m] interleaved

__device__ __forceinline__ u64 pack2(float lo, float hi) {
    u64 r; asm("mov.b64 %0, {%1,%2};" : "=l"(r) : "f"(lo), "f"(hi)); return r;
}
__device__ __forceinline__ void unpack2(u64 v, float& lo, float& hi) {
    asm("mov.b64 {%0,%1}, %2;" : "=f"(lo), "=f"(hi) : "l"(v));
}
__device__ __forceinline__ void fma2(u64& d, u64 a, u64 b) {
    asm("fma.rn.f32x2 %0, %1, %2, %0;" : "+l"(d) : "l"(a), "l"(b));
}
__device__ __forceinline__ u64 add2(u64 a, u64 b) {
    u64 r; asm("add.rn.f32x2 %0, %1, %2;" : "=l"(r) : "l"(a), "l"(b)); return r;
}

// ---------------------------------------------------------------------------
// Kernel 1: 1x1 reduce conv with IN-BLOCK channel-split reduction.
// 512 threads = 4 slice-groups x 128 threads over the SAME 512 pixels.
// Each thread: 4 px x 64 channels -> partial; smem tree combines the 4
// slices and writes xlow ONCE (kills the 134MB partial round-trip of R7).
// Dynamic smem: 16KB weights + 64KB reduce buffer = 80KB.
// ---------------------------------------------------------------------------
__global__ __launch_bounds__(512) void k_reduce(const float* __restrict__ x,
                                                const float* __restrict__ rw) {
    extern __shared__ __align__(16) char dynsmem[];
    float* s_rw = (float*)dynsmem;                       // [slice][c_loc][m], 16KB
    ulonglong2* s_buf = (ulonglong2*)(dynsmem + 16384);  // [k2][sp][t], 64KB

    int tid = threadIdx.x;
    int s = tid >> 7;            // slice 0..3 (channels s*64 .. s*64+63)
    int t = tid & 127;           // thread within slice (pixel group)

    for (int i = tid; i < 4096; i += 512) {
        int sl = i >> 10, r = i & 1023;
        int cl = r >> 4, m = r & 15;
        s_rw[i] = rw[m * 256 + sl * 64 + cl];
    }
    __syncthreads();

    int gp4 = (blockIdx.x * 128 + t) * 4;    // base pixel over B*HW (512 px/block)
    int b = gp4 >> 16, p = gp4 & 65535;
    const float* xb = x + (size_t)b * (Cc * HWc) + (size_t)(s * 64) * HWc + p;
    const ulonglong2* srw = (const ulonglong2*)(s_rw + (s << 10));

    u64 acc[4][8];
#pragma unroll
    for (int px = 0; px < 4; px++)
#pragma unroll
        for (int m = 0; m < 8; m++) acc[px][m] = 0ull;

#pragma unroll 4
    for (int cl = 0; cl < 64; cl++) {
        float4 xv = *(const float4*)(xb + (size_t)cl * HWc);
        u64 xd0 = pack2(xv.x, xv.x);
        u64 xd1 = pack2(xv.y, xv.y);
        u64 xd2 = pack2(xv.z, xv.z);
        u64 xd3 = pack2(xv.w, xv.w);
        ulonglong2 w0 = srw[cl * 4 + 0];
        ulonglong2 w1 = srw[cl * 4 + 1];
        ulonglong2 w2 = srw[cl * 4 + 2];
        ulonglong2 w3 = srw[cl * 4 + 3];
        fma2(acc[0][0], xd0, w0.x); fma2(acc[0][1], xd0, w0.y);
        fma2(acc[0][2], xd0, w1.x); fma2(acc[0][3], xd0, w1.y);
        fma2(acc[0][4], xd0, w2.x); fma2(acc[0][5], xd0, w2.y);
        fma2(acc[0][6], xd0, w3.x); fma2(acc[0][7], xd0, w3.y);
        fma2(acc[1][0], xd1, w0.x); fma2(acc[1][1], xd1, w0.y);
        fma2(acc[1][2], xd1, w1.x); fma2(acc[1][3], xd1, w1.y);
        fma2(acc[1][4], xd1, w2.x); fma2(acc[1][5], xd1, w2.y);
        fma2(acc[1][6], xd1, w3.x); fma2(acc[1][7], xd1, w3.y);
        fma2(acc[2][0], xd2, w0.x); fma2(acc[2][1], xd2, w0.y);
        fma2(acc[2][2], xd2, w1.x); fma2(acc[2][3], xd2, w1.y);
        fma2(acc[2][4], xd2, w2.x); fma2(acc[2][5], xd2, w2.y);
        fma2(acc[2][6], xd2, w3.x); fma2(acc[2][7], xd2, w3.y);
        fma2(acc[3][0], xd3, w0.x); fma2(acc[3][1], xd3, w0.y);
        fma2(acc[3][2], xd3, w1.x); fma2(acc[3][3], xd3, w1.y);
        fma2(acc[3][4], xd3, w2.x); fma2(acc[3][5], xd3, w2.y);
        fma2(acc[3][6], xd3, w3.x); fma2(acc[3][7], xd3, w3.y);
    }

    // Cross-slice tree: (s2,s3) dump -> (s0,s1) add; s1 dump -> s0 add.
    // Buffer layout [k2][sp][t] keeps consecutive t on consecutive 16B: no
    // bank conflicts. k2 = px*4 + j packs (acc[px][2j], acc[px][2j+1]).
    if (s >= 2) {
        ulonglong2* bp = s_buf + (size_t)(s - 2) * 128 + t;
#pragma unroll
        for (int px = 0; px < 4; px++)
#pragma unroll
            for (int j = 0; j < 4; j++) {
                ulonglong2 v; v.x = acc[px][2 * j]; v.y = acc[px][2 * j + 1];
                bp[(px * 4 + j) * 256] = v;
            }
    }
    __syncthreads();
    if (s < 2) {
        const ulonglong2* bp = s_buf + (size_t)s * 128 + t;
#pragma unroll
        for (int px = 0; px < 4; px++)
#pragma unroll
            for (int j = 0; j < 4; j++) {
                ulonglong2 v = bp[(px * 4 + j) * 256];
                acc[px][2 * j]     = add2(acc[px][2 * j], v.x);
                acc[px][2 * j + 1] = add2(acc[px][2 * j + 1], v.y);
            }
    }
    __syncthreads();
    if (s == 1) {
        ulonglong2* bp = s_buf + t;
#pragma unroll
        for (int px = 0; px < 4; px++)
#pragma unroll
            for (int j = 0; j < 4; j++) {
                ulonglong2 v; v.x = acc[px][2 * j]; v.y = acc[px][2 * j + 1];
                bp[(px * 4 + j) * 256] = v;
            }
    }
    __syncthreads();
    if (s == 0) {
        const ulonglong2* bp = s_buf + t;
#pragma unroll
        for (int px = 0; px < 4; px++) {
            ulonglong2* dst = (ulonglong2*)(g_xlow + (size_t)(gp4 + px) * 16);
#pragma unroll
            for (int j = 0; j < 4; j++) {
                ulonglong2 v = bp[(px * 4 + j) * 256];
                ulonglong2 r;
                r.x = add2(acc[px][2 * j], v.x);
                r.y = add2(acc[px][2 * j + 1], v.y);
                dst[j] = r;
            }
        }
    }
}

// ---------------------------------------------------------------------------
// Kernel 2: fused base-kernel build + angle-MLP + softmax + 7x7 directional
// conv. Tile 32x8 pixels, halo 3 (reflect), 16 channels in smem with rotation
// swizzle for conflict-free LDS.128. Reads the single xlow buffer.
// ---------------------------------------------------------------------------
__global__ __launch_bounds__(256) void k_conv(const float* __restrict__ angle,
                                              const float* __restrict__ w1,
                                              const float* __restrict__ b1,
                                              const float* __restrict__ w2,
                                              const float* __restrict__ b2) {
    __shared__ __align__(16) float s_x[14 * 38 * 16];  // 34 KB, swizzled
    __shared__ float s_base[196];
    __shared__ float s_sinv[4];
    __shared__ float s_w1[16], s_b1[8], s_w2[32], s_b2[4];

    int tx = threadIdx.x, ty = threadIdx.y;
    int tid = ty * 32 + tx;
    int x0 = blockIdx.x * 32, y0 = blockIdx.y * 8, b = blockIdx.z;

    // Build the 4 oriented anisotropic Gaussian kernels (unnormalized).
    if (tid < 196) {
        int k = tid / 49, r = tid - k * 49;
        int ii = r / 7 - 3, jj = r % 7 - 3;
        float theta = (float)k * (float)(CUDART_PI / 4.0);
        float cth, sth;
        sincosf(theta, &sth, &cth);
        float xr = (float)ii * cth + (float)jj * sth;
        float yr = -(float)ii * sth + (float)jj * cth;
        s_base[tid] = expf(-(xr * xr * 0.08f + yr * yr * 0.5f));
    }
    if (tid < 16) s_w1[tid] = w1[tid];
    if (tid < 8)  s_b1[tid] = b1[tid];
    if (tid < 32) s_w2[tid] = w2[tid];
    if (tid < 4)  s_b2[tid] = b2[tid];

    // Load halo tile with reflect padding, swizzled store.
    for (int i = tid; i < 14 * 38 * 4; i += 256) {
        int pl = i >> 2, g = i & 3;
        int ry = pl / 38, rx = pl - ry * 38;
        int gy = y0 + ry - 3; gy = gy < 0 ? -gy : (gy > 255 ? 510 - gy : gy);
        int gx = x0 + rx - 3; gx = gx < 0 ? -gx : (gx > 255 ? 510 - gx : gx);
        const float4* src = (const float4*)(g_xlow + ((size_t)((b << 16) + (gy << 8) + gx)) * 16);
        int slot = (g + (pl >> 1)) & 3;
        *(float4*)(s_x + pl * 16 + slot * 4) = src[g];
    }
    __syncthreads();

    // Deterministic per-kernel normalization sums.
    if (tid < 4) {
        float sum = 0.f;
        for (int t = 0; t < 49; t++) sum += s_base[tid * 49 + t];
        s_sinv[tid] = 1.f / sum;
    }
    __syncthreads();

    int px = x0 + tx, py = y0 + ty;

    // Per-pixel mixing weights: MLP(2->8->4) + softmax.
    float a = angle[(size_t)((b << 16) + (py << 8) + px)];
    float sn, cs;
    sincosf(2.f * a, &sn, &cs);
    float hb[8];
#pragma unroll
    for (int j = 0; j < 8; j++)
        hb[j] = fmaxf(0.f, fmaf(sn, s_w1[2 * j], fmaf(cs, s_w1[2 * j + 1], s_b1[j])));
    float lg[4];
#pragma unroll
    for (int o = 0; o < 4; o++) {
        float t = s_b2[o];
#pragma unroll
        for (int j = 0; j < 8; j++) t = fmaf(hb[j], s_w2[o * 8 + j], t);
        lg[o] = t;
    }
    float mx = fmaxf(fmaxf(lg[0], lg[1]), fmaxf(lg[2], lg[3]));
    float wk[4];
    float sum = 0.f;
#pragma unroll
    for (int o = 0; o < 4; o++) { wk[o] = expf(lg[o] - mx); sum += wk[o]; }
    float inv = 1.f / sum;
#pragma unroll
    for (int o = 0; o < 4; o++) wk[o] *= inv * s_sinv[o];  // fold base normalization

    // Combined per-pixel 7x7 kernel.
    float ck[49];
#pragma unroll
    for (int t = 0; t < 49; t++)
        ck[t] = fmaf(wk[3], s_base[147 + t],
                fmaf(wk[2], s_base[98 + t],
                fmaf(wk[1], s_base[49 + t], wk[0] * s_base[t])));

    u64 acc[8];
#pragma unroll
    for (int q = 0; q < 8; q++) acc[q] = 0ull;
    const ulonglong2* sx2 = (const ulonglong2*)s_x;

#pragma unroll
    for (int i = 0; i < 7; i++) {
#pragma unroll
        for (int j = 0; j < 7; j++) {
            int pl = (ty + i) * 38 + tx + j;
            int base4 = pl * 4;
            int r = (pl >> 1) & 3;
            u64 ckd = pack2(ck[i * 7 + j], ck[i * 7 + j]);
            ulonglong2 v0 = sx2[base4 + ((0 + r) & 3)];
            ulonglong2 v1 = sx2[base4 + ((1 + r) & 3)];
            ulonglong2 v2 = sx2[base4 + ((2 + r) & 3)];
            ulonglong2 v3 = sx2[base4 + ((3 + r) & 3)];
            fma2(acc[0], v0.x, ckd); fma2(acc[1], v0.y, ckd);
            fma2(acc[2], v1.x, ckd); fma2(acc[3], v1.y, ckd);
            fma2(acc[4], v2.x, ckd); fma2(acc[5], v2.y, ckd);
            fma2(acc[6], v3.x, ckd); fma2(acc[7], v3.y, ckd);
        }
    }

    ulonglong2* dst = (ulonglong2*)(g_outlow + (size_t)((b << 16) + (py << 8) + px) * 16);
    ulonglong2 r0; r0.x = acc[0]; r0.y = acc[1]; dst[0] = r0;
    ulonglong2 r1; r1.x = acc[2]; r1.y = acc[3]; dst[1] = r1;
    ulonglong2 r2; r2.x = acc[4]; r2.y = acc[5]; dst[2] = r2;
    ulonglong2 r3; r3.x = acc[6]; r3.y = acc[7]; dst[3] = r3;
}

// ---------------------------------------------------------------------------
// Kernel 3: 1x1 expand conv  outlow[b,p,m] * ew[c,m] -> out[b,c,h,w]
// 4 pixels/thread, 4 channel-groups of 64: 131072 threads total.
// grid (128, 4) x 256 threads.
// ---------------------------------------------------------------------------
__global__ __launch_bounds__(256) void k_expand(const float* __restrict__ ew,
                                                float* __restrict__ out) {
    __shared__ __align__(16) float s_ew[1024];  // [c_loc][m], 4 KB
    int tid = threadIdx.x;
    int c0 = blockIdx.y * 64;
    for (int i = tid; i < 1024; i += 256) s_ew[i] = ew[c0 * 16 + i];
    __syncthreads();

    int gp4 = (blockIdx.x * 256 + tid) * 4;     // base pixel over B*HW
    int b = gp4 >> 16, p = gp4 & 65535;

    // Load 4 pixels x 16 mids; memory already pairs (m0,m1) in adjacent floats.
    u64 xp[4][8];
#pragma unroll
    for (int px = 0; px < 4; px++) {
        const ulonglong2* s2 = (const ulonglong2*)(g_outlow + (size_t)(gp4 + px) * 16);
        ulonglong2 t0 = s2[0], t1 = s2[1], t2 = s2[2], t3 = s2[3];
        xp[px][0] = t0.x; xp[px][1] = t0.y;
        xp[px][2] = t1.x; xp[px][3] = t1.y;
        xp[px][4] = t2.x; xp[px][5] = t2.y;
        xp[px][6] = t3.x; xp[px][7] = t3.y;
    }

    const ulonglong2* sew = (const ulonglong2*)s_ew;
    float* ob = out + (size_t)b * (Cc * HWc) + (size_t)c0 * HWc + p;

#pragma unroll 4
    for (int cl = 0; cl < 64; cl++) {
        ulonglong2 w0 = sew[cl * 4 + 0];
        ulonglong2 w1 = sew[cl * 4 + 1];
        ulonglong2 w2 = sew[cl * 4 + 2];
        ulonglong2 w3 = sew[cl * 4 + 3];
        float4 r;
#pragma unroll
        for (int px = 0; px < 4; px++) {
            u64 a = 0ull;
            fma2(a, xp[px][0], w0.x); fma2(a, xp[px][1], w0.y);
            fma2(a, xp[px][2], w1.x); fma2(a, xp[px][3], w1.y);
            fma2(a, xp[px][4], w2.x); fma2(a, xp[px][5], w2.y);
            fma2(a, xp[px][6], w3.x); fma2(a, xp[px][7], w3.y);
            float lo, hi; unpack2(a, lo, hi);
            float v = lo + hi;
            if (px == 0) r.x = v; else if (px == 1) r.y = v;
            else if (px == 2) r.z = v; else r.w = v;
        }
        *(float4*)(ob + (size_t)cl * HWc) = r;
    }
}

// ---------------------------------------------------------------------------
extern "C" void kernel_launch(void* const* d_in, const int* in_sizes, int n_in,
                              void* d_out, int out_size) {
    const float* x     = (const float*)d_in[0];
    const float* angle = (const float*)d_in[1];
    const float* rw    = (const float*)d_in[2];
    const float* ew    = (const float*)d_in[3];
    const float* w1    = (const float*)d_in[4];
    const float* b1    = (const float*)d_in[5];
    const float* w2    = (const float*)d_in[6];
    const float* b2    = (const float*)d_in[7];
    float* out = (float*)d_out;

    const int REDUCE_SMEM = 16384 + 65536;  // 80KB dynamic
    cudaFuncSetAttribute(k_reduce, cudaFuncAttributeMaxDynamicSharedMemorySize,
                         REDUCE_SMEM);

    k_reduce<<<256, 512, REDUCE_SMEM>>>(x, rw);
    k_conv<<<dim3(8, 32, 2), dim3(32, 8)>>>(angle, w1, b1, w2, b2);
    k_expand<<<dim3(128, 4), 256>>>(ew, out);
}

// round 14
// speedup vs baseline: 1.0613x; 1.0613x over previous
#include <cuda_runtime.h>
#include <cuda_bf16.h>
#include <math_constants.h>

#define Bc 2
#define Cc 256
#define Hc 256
#define Wc 256
#define MIDc 16
#define HWc 65536

typedef unsigned long long u64;

__device__ float g_xlow[(size_t)Bc * HWc * MIDc];    // [b][p][m] interleaved
__device__ float g_outlow[(size_t)Bc * HWc * MIDc];  // [b][p][m] interleaved

__device__ __forceinline__ u64 pack2(float lo, float hi) {
    u64 r; asm("mov.b64 %0, {%1,%2};" : "=l"(r) : "f"(lo), "f"(hi)); return r;
}
__device__ __forceinline__ void unpack2(u64 v, float& lo, float& hi) {
    asm("mov.b64 {%0,%1}, %2;" : "=f"(lo), "=f"(hi) : "l"(v));
}
__device__ __forceinline__ void fma2(u64& d, u64 a, u64 b) {
    asm("fma.rn.f32x2 %0, %1, %2, %0;" : "+l"(d) : "l"(a), "l"(b));
}
__device__ __forceinline__ u64 add2(u64 a, u64 b) {
    u64 r; asm("add.rn.f32x2 %0, %1, %2;" : "=l"(r) : "l"(a), "l"(b)); return r;
}

// ---------------------------------------------------------------------------
// Kernel 1: 1x1 reduce conv with in-block channel-split reduction.
// 128 threads = 4 slice-groups x 32 px-threads over the SAME 128 pixels.
// Each thread: 4 px x 64 channels -> partial; 2-round smem tree combines the
// 4 slices; xlow written once. Grid 1024: 4 blocks/SM (13.8K regs/block),
// fine-grained waves. smem 32KB static.
// ---------------------------------------------------------------------------
__global__ __launch_bounds__(128) void k_reduce(const float* __restrict__ x,
                                                const float* __restrict__ rw) {
    __shared__ __align__(16) float s_rw[4096];        // [slice][c_loc][m], 16KB
    __shared__ __align__(16) ulonglong2 s_buf[1024];  // [k2][sp][t], 16KB

    int tid = threadIdx.x;
    int s = tid >> 5;            // slice 0..3 (channels s*64 .. s*64+63)
    int t = tid & 31;            // px-thread within slice (= lane)

    for (int i = tid; i < 4096; i += 128) {
        int sl = i >> 10, r = i & 1023;
        int cl = r >> 4, m = r & 15;
        s_rw[i] = rw[m * 256 + sl * 64 + cl];
    }
    __syncthreads();

    int gp4 = (blockIdx.x * 32 + t) * 4;     // base pixel over B*HW (128 px/block)
    int b = gp4 >> 16, p = gp4 & 65535;
    const float* xb = x + (size_t)b * (Cc * HWc) + (size_t)(s * 64) * HWc + p;
    const ulonglong2* srw = (const ulonglong2*)(s_rw + (s << 10));

    u64 acc[4][8];
#pragma unroll
    for (int px = 0; px < 4; px++)
#pragma unroll
        for (int m = 0; m < 8; m++) acc[px][m] = 0ull;

#pragma unroll 4
    for (int cl = 0; cl < 64; cl++) {
        float4 xv = *(const float4*)(xb + (size_t)cl * HWc);
        u64 xd0 = pack2(xv.x, xv.x);
        u64 xd1 = pack2(xv.y, xv.y);
        u64 xd2 = pack2(xv.z, xv.z);
        u64 xd3 = pack2(xv.w, xv.w);
        ulonglong2 w0 = srw[cl * 4 + 0];
        ulonglong2 w1 = srw[cl * 4 + 1];
        ulonglong2 w2 = srw[cl * 4 + 2];
        ulonglong2 w3 = srw[cl * 4 + 3];
        fma2(acc[0][0], xd0, w0.x); fma2(acc[0][1], xd0, w0.y);
        fma2(acc[0][2], xd0, w1.x); fma2(acc[0][3], xd0, w1.y);
        fma2(acc[0][4], xd0, w2.x); fma2(acc[0][5], xd0, w2.y);
        fma2(acc[0][6], xd0, w3.x); fma2(acc[0][7], xd0, w3.y);
        fma2(acc[1][0], xd1, w0.x); fma2(acc[1][1], xd1, w0.y);
        fma2(acc[1][2], xd1, w1.x); fma2(acc[1][3], xd1, w1.y);
        fma2(acc[1][4], xd1, w2.x); fma2(acc[1][5], xd1, w2.y);
        fma2(acc[1][6], xd1, w3.x); fma2(acc[1][7], xd1, w3.y);
        fma2(acc[2][0], xd2, w0.x); fma2(acc[2][1], xd2, w0.y);
        fma2(acc[2][2], xd2, w1.x); fma2(acc[2][3], xd2, w1.y);
        fma2(acc[2][4], xd2, w2.x); fma2(acc[2][5], xd2, w2.y);
        fma2(acc[2][6], xd2, w3.x); fma2(acc[2][7], xd2, w3.y);
        fma2(acc[3][0], xd3, w0.x); fma2(acc[3][1], xd3, w0.y);
        fma2(acc[3][2], xd3, w1.x); fma2(acc[3][3], xd3, w1.y);
        fma2(acc[3][4], xd3, w2.x); fma2(acc[3][5], xd3, w2.y);
        fma2(acc[3][6], xd3, w3.x); fma2(acc[3][7], xd3, w3.y);
    }

    // Cross-slice tree: (s2,s3) dump -> (s0,s1) add; s1 dump -> s0 add+store.
    // Index (px*4+j)*64 + sp*32 + t: consecutive t on consecutive 16B ->
    // conflict-free 512B warp transactions.
    if (s >= 2) {
        ulonglong2* bp = s_buf + (s - 2) * 32 + t;
#pragma unroll
        for (int px = 0; px < 4; px++)
#pragma unroll
            for (int j = 0; j < 4; j++) {
                ulonglong2 v; v.x = acc[px][2 * j]; v.y = acc[px][2 * j + 1];
                bp[(px * 4 + j) * 64] = v;
            }
    }
    __syncthreads();
    if (s < 2) {
        const ulonglong2* bp = s_buf + s * 32 + t;
#pragma unroll
        for (int px = 0; px < 4; px++)
#pragma unroll
            for (int j = 0; j < 4; j++) {
                ulonglong2 v = bp[(px * 4 + j) * 64];
                acc[px][2 * j]     = add2(acc[px][2 * j], v.x);
                acc[px][2 * j + 1] = add2(acc[px][2 * j + 1], v.y);
            }
    }
    __syncthreads();
    if (s == 1) {
        ulonglong2* bp = s_buf + t;
#pragma unroll
        for (int px = 0; px < 4; px++)
#pragma unroll
            for (int j = 0; j < 4; j++) {
                ulonglong2 v; v.x = acc[px][2 * j]; v.y = acc[px][2 * j + 1];
                bp[(px * 4 + j) * 64] = v;
            }
    }
    __syncthreads();
    if (s == 0) {
        const ulonglong2* bp = s_buf + t;
#pragma unroll
        for (int px = 0; px < 4; px++) {
            ulonglong2* dst = (ulonglong2*)(g_xlow + (size_t)(gp4 + px) * 16);
#pragma unroll
            for (int j = 0; j < 4; j++) {
                ulonglong2 v = bp[(px * 4 + j) * 64];
                ulonglong2 r;
                r.x = add2(acc[px][2 * j], v.x);
                r.y = add2(acc[px][2 * j + 1], v.y);
                dst[j] = r;
            }
        }
    }
}

// ---------------------------------------------------------------------------
// Kernel 2: fused base-kernel build + angle-MLP + softmax + 7x7 directional
// conv. Tile 32x8, halo 3 (reflect), rotation-swizzled smem. Per-tap combined
// kernel computed inline (no ck[49] register array -> ~64 regs, 4 blocks/SM).
// ---------------------------------------------------------------------------
__global__ __launch_bounds__(256) void k_conv(const float* __restrict__ angle,
                                              const float* __restrict__ w1,
                                              const float* __restrict__ b1,
                                              const float* __restrict__ w2,
                                              const float* __restrict__ b2) {
    __shared__ __align__(16) float s_x[14 * 38 * 16];  // 34 KB, swizzled
    __shared__ float s_base[196];
    __shared__ float s_sinv[4];
    __shared__ float s_w1[16], s_b1[8], s_w2[32], s_b2[4];

    int tx = threadIdx.x, ty = threadIdx.y;
    int tid = ty * 32 + tx;
    int x0 = blockIdx.x * 32, y0 = blockIdx.y * 8, b = blockIdx.z;

    // Build the 4 oriented anisotropic Gaussian kernels (unnormalized).
    if (tid < 196) {
        int k = tid / 49, r = tid - k * 49;
        int ii = r / 7 - 3, jj = r % 7 - 3;
        float theta = (float)k * (float)(CUDART_PI / 4.0);
        float cth, sth;
        sincosf(theta, &sth, &cth);
        float xr = (float)ii * cth + (float)jj * sth;
        float yr = -(float)ii * sth + (float)jj * cth;
        s_base[tid] = expf(-(xr * xr * 0.08f + yr * yr * 0.5f));
    }
    if (tid < 16) s_w1[tid] = w1[tid];
    if (tid < 8)  s_b1[tid] = b1[tid];
    if (tid < 32) s_w2[tid] = w2[tid];
    if (tid < 4)  s_b2[tid] = b2[tid];

    // Load halo tile with reflect padding, swizzled store.
    for (int i = tid; i < 14 * 38 * 4; i += 256) {
        int pl = i >> 2, g = i & 3;
        int ry = pl / 38, rx = pl - ry * 38;
        int gy = y0 + ry - 3; gy = gy < 0 ? -gy : (gy > 255 ? 510 - gy : gy);
        int gx = x0 + rx - 3; gx = gx < 0 ? -gx : (gx > 255 ? 510 - gx : gx);
        const float4* src = (const float4*)(g_xlow + ((size_t)((b << 16) + (gy << 8) + gx)) * 16);
        int slot = (g + (pl >> 1)) & 3;
        *(float4*)(s_x + pl * 16 + slot * 4) = src[g];
    }
    __syncthreads();

    // Deterministic per-kernel normalization sums.
    if (tid < 4) {
        float sum = 0.f;
        for (int t = 0; t < 49; t++) sum += s_base[tid * 49 + t];
        s_sinv[tid] = 1.f / sum;
    }
    __syncthreads();

    int px = x0 + tx, py = y0 + ty;

    // Per-pixel mixing weights: MLP(2->8->4) + softmax.
    float a = angle[(size_t)((b << 16) + (py << 8) + px)];
    float sn, cs;
    sincosf(2.f * a, &sn, &cs);
    float hb[8];
#pragma unroll
    for (int j = 0; j < 8; j++)
        hb[j] = fmaxf(0.f, fmaf(sn, s_w1[2 * j], fmaf(cs, s_w1[2 * j + 1], s_b1[j])));
    float lg[4];
#pragma unroll
    for (int o = 0; o < 4; o++) {
        float t = s_b2[o];
#pragma unroll
        for (int j = 0; j < 8; j++) t = fmaf(hb[j], s_w2[o * 8 + j], t);
        lg[o] = t;
    }
    float mx = fmaxf(fmaxf(lg[0], lg[1]), fmaxf(lg[2], lg[3]));
    float wk0, wk1, wk2, wk3;
    wk0 = expf(lg[0] - mx); wk1 = expf(lg[1] - mx);
    wk2 = expf(lg[2] - mx); wk3 = expf(lg[3] - mx);
    float inv = 1.f / (wk0 + wk1 + wk2 + wk3);
    wk0 *= inv * s_sinv[0];  // fold base normalization
    wk1 *= inv * s_sinv[1];
    wk2 *= inv * s_sinv[2];
    wk3 *= inv * s_sinv[3];

    u64 acc[8];
#pragma unroll
    for (int q = 0; q < 8; q++) acc[q] = 0ull;
    const ulonglong2* sx2 = (const ulonglong2*)s_x;

#pragma unroll
    for (int i = 0; i < 7; i++) {
#pragma unroll
        for (int j = 0; j < 7; j++) {
            int tt = i * 7 + j;
            // Combined tap weight computed inline (saves 49 regs).
            float ckt = fmaf(wk3, s_base[147 + tt],
                        fmaf(wk2, s_base[98 + tt],
                        fmaf(wk1, s_base[49 + tt], wk0 * s_base[tt])));
            int pl = (ty + i) * 38 + tx + j;
            int base4 = pl * 4;
            int r = (pl >> 1) & 3;
            u64 ckd = pack2(ckt, ckt);
            ulonglong2 v0 = sx2[base4 + ((0 + r) & 3)];
            ulonglong2 v1 = sx2[base4 + ((1 + r) & 3)];
            ulonglong2 v2 = sx2[base4 + ((2 + r) & 3)];
            ulonglong2 v3 = sx2[base4 + ((3 + r) & 3)];
            fma2(acc[0], v0.x, ckd); fma2(acc[1], v0.y, ckd);
            fma2(acc[2], v1.x, ckd); fma2(acc[3], v1.y, ckd);
            fma2(acc[4], v2.x, ckd); fma2(acc[5], v2.y, ckd);
            fma2(acc[6], v3.x, ckd); fma2(acc[7], v3.y, ckd);
        }
    }

    ulonglong2* dst = (ulonglong2*)(g_outlow + (size_t)((b << 16) + (py << 8) + px) * 16);
    ulonglong2 r0; r0.x = acc[0]; r0.y = acc[1]; dst[0] = r0;
    ulonglong2 r1; r1.x = acc[2]; r1.y = acc[3]; dst[1] = r1;
    ulonglong2 r2; r2.x = acc[4]; r2.y = acc[5]; dst[2] = r2;
    ulonglong2 r3; r3.x = acc[6]; r3.y = acc[7]; dst[3] = r3;
}

// ---------------------------------------------------------------------------
// Kernel 3: 1x1 expand conv  outlow[b,p,m] * ew[c,m] -> out[b,c,h,w]
// 4 pixels/thread, 4 channel-groups of 64. 128-thread blocks (5 blocks/SM)
// for finer waves. grid (256, 4) x 128 threads.
// ---------------------------------------------------------------------------
__global__ __launch_bounds__(128) void k_expand(const float* __restrict__ ew,
                                                float* __restrict__ out) {
    __shared__ __align__(16) float s_ew[1024];  // [c_loc][m], 4 KB
    int tid = threadIdx.x;
    int c0 = blockIdx.y * 64;
    for (int i = tid; i < 1024; i += 128) s_ew[i] = ew[c0 * 16 + i];
    __syncthreads();

    int gp4 = (blockIdx.x * 128 + tid) * 4;     // base pixel over B*HW
    int b = gp4 >> 16, p = gp4 & 65535;

    // Load 4 pixels x 16 mids; memory already pairs (m0,m1) in adjacent floats.
    u64 xp[4][8];
#pragma unroll
    for (int px = 0; px < 4; px++) {
        const ulonglong2* s2 = (const ulonglong2*)(g_outlow + (size_t)(gp4 + px) * 16);
        ulonglong2 t0 = s2[0], t1 = s2[1], t2 = s2[2], t3 = s2[3];
        xp[px][0] = t0.x; xp[px][1] = t0.y;
        xp[px][2] = t1.x; xp[px][3] = t1.y;
        xp[px][4] = t2.x; xp[px][5] = t2.y;
        xp[px][6] = t3.x; xp[px][7] = t3.y;
    }

    const ulonglong2* sew = (const ulonglong2*)s_ew;
    float* ob = out + (size_t)b * (Cc * HWc) + (size_t)c0 * HWc + p;

#pragma unroll 4
    for (int cl = 0; cl < 64; cl++) {
        ulonglong2 w0 = sew[cl * 4 + 0];
        ulonglong2 w1 = sew[cl * 4 + 1];
        ulonglong2 w2 = sew[cl * 4 + 2];
        ulonglong2 w3 = sew[cl * 4 + 3];
        float4 r;
#pragma unroll
        for (int px = 0; px < 4; px++) {
            u64 a = 0ull;
            fma2(a, xp[px][0], w0.x); fma2(a, xp[px][1], w0.y);
            fma2(a, xp[px][2], w1.x); fma2(a, xp[px][3], w1.y);
            fma2(a, xp[px][4], w2.x); fma2(a, xp[px][5], w2.y);
            fma2(a, xp[px][6], w3.x); fma2(a, xp[px][7], w3.y);
            float lo, hi; unpack2(a, lo, hi);
            float v = lo + hi;
            if (px == 0) r.x = v; else if (px == 1) r.y = v;
            else if (px == 2) r.z = v; else r.w = v;
        }
        *(float4*)(ob + (size_t)cl * HWc) = r;
    }
}

// ---------------------------------------------------------------------------
extern "C" void kernel_launch(void* const* d_in, const int* in_sizes, int n_in,
                              void* d_out, int out_size) {
    const float* x     = (const float*)d_in[0];
    const float* angle = (const float*)d_in[1];
    const float* rw    = (const float*)d_in[2];
    const float* ew    = (const float*)d_in[3];
    const float* w1    = (const float*)d_in[4];
    const float* b1    = (const float*)d_in[5];
    const float* w2    = (const float*)d_in[6];
    const float* b2    = (const float*)d_in[7];
    float* out = (float*)d_out;

    k_reduce<<<1024, 128>>>(x, rw);
    k_conv<<<dim3(8, 32, 2), dim3(32, 8)>>>(angle, w1, b1, w2, b2);
    k_expand<<<dim3(256, 4), 128>>>(ew, out);
}